// round 6
// baseline (speedup 1.0000x reference)
#include <cuda_runtime.h>
#include <cstdint>

#define N_MAX 100000
#define E_MAX 1000000
#define D 64
#define D4 16               // D/4 float4 per row
#define TILE_ROWS 128
#define SCAN_B 1024

// Scratch (static device globals — no allocations allowed)
__device__ int    g_deg     [N_MAX];
__device__ int    g_rowptr  [N_MAX + 1];
__device__ int    g_cursor  [N_MAX];
__device__ int    g_srcsort [E_MAX];
__device__ int    g_bsums   [128];
__device__ float  s_dinv    [N_MAX];
__device__ float4 s_g       [N_MAX * D4];   // features (gather source)
__device__ float4 s_y       [N_MAX * D4];   // layer-1 output

// ---------------------------------------------------------------------------
// Shared GEMM body: h = X @ W ; optionally scale rows by dinv before store.
// 256 threads, 128 rows/block. Thread = 8 rows x 4 cols.
__device__ __forceinline__ void gemm_body(
    const float* __restrict__ X, const float* __restrict__ W,
    int n, int row0, bool apply_dinv,
    float4* ws, float4* xs)
{
    const int tid = threadIdx.x;

    const float4* W4 = (const float4*)W;
    #pragma unroll
    for (int i = tid; i < D * D4; i += 256) ws[i] = __ldg(&W4[i]);

    const float4* X4 = (const float4*)X;
    #pragma unroll
    for (int i = tid; i < TILE_ROWS * D4; i += 256) {
        int rr = i >> 4;
        float4 v = make_float4(0.f, 0.f, 0.f, 0.f);
        if (row0 + rr < n) v = __ldg(&X4[(row0 + rr) * D4 + (i & 15)]);
        xs[i] = v;
    }
    __syncthreads();

    const int cg = tid & 15;   // col group
    const int rg = tid >> 4;   // row group

    float acc[8][4];
    #pragma unroll
    for (int r = 0; r < 8; r++)
        #pragma unroll
        for (int c = 0; c < 4; c++) acc[r][c] = 0.f;

    #pragma unroll 2
    for (int k = 0; k < D; k += 4) {
        float4 w0 = ws[(k + 0) * D4 + cg];
        float4 w1 = ws[(k + 1) * D4 + cg];
        float4 w2 = ws[(k + 2) * D4 + cg];
        float4 w3 = ws[(k + 3) * D4 + cg];
        #pragma unroll
        for (int r = 0; r < 8; r++) {
            float4 xv = xs[(rg * 8 + r) * D4 + (k >> 2)];
            acc[r][0] += xv.x * w0.x + xv.y * w1.x + xv.z * w2.x + xv.w * w3.x;
            acc[r][1] += xv.x * w0.y + xv.y * w1.y + xv.z * w2.y + xv.w * w3.y;
            acc[r][2] += xv.x * w0.z + xv.y * w1.z + xv.z * w2.z + xv.w * w3.z;
            acc[r][3] += xv.x * w0.w + xv.y * w1.w + xv.z * w2.w + xv.w * w3.w;
        }
    }

    #pragma unroll
    for (int r = 0; r < 8; r++) {
        int row = row0 + rg * 8 + r;
        if (row < n) {
            float dv = apply_dinv ? s_dinv[row] : 1.0f;
            s_g[row * D4 + cg] =
                make_float4(acc[r][0] * dv, acc[r][1] * dv,
                            acc[r][2] * dv, acc[r][3] * dv);
        }
    }
}

// ---------------------------------------------------------------------------
// Heterogeneous kernel: blocks [0, nb_gmm) run GEMM1 (unscaled h1 -> s_g),
// blocks [nb_gmm, ...) run the dst-degree histogram. Independent work,
// co-resident on the chip.
__global__ __launch_bounds__(256) void gemm1_hist_kernel(
    const float* __restrict__ X, const float* __restrict__ W,
    const int* __restrict__ ei, int n, int E, int nb_gmm)
{
    __shared__ float4 ws[D * D4];
    __shared__ float4 xs[TILE_ROWS * D4];

    if ((int)blockIdx.x < nb_gmm) {
        gemm_body(X, W, n, blockIdx.x * TILE_ROWS, /*apply_dinv=*/false, ws, xs);
    } else {
        int bi = blockIdx.x - nb_gmm;
        int nE4 = E >> 2;
        int i = bi * 256 + threadIdx.x;
        if (i < nE4) {
            int4 d = __ldg(&((const int4*)(ei + E))[i]);
            atomicAdd(&g_deg[d.x], 1);
            atomicAdd(&g_deg[d.y], 1);
            atomicAdd(&g_deg[d.z], 1);
            atomicAdd(&g_deg[d.w], 1);
        }
        // tail (E % 4)
        if (bi == 0 && threadIdx.x < (E & 3))
            atomicAdd(&g_deg[ei[E + (E & ~3) + threadIdx.x]], 1);
    }
}

// ---------------------------------------------------------------------------
// exclusive scan, stage 1: shuffle-based per-block scan + block totals
__global__ __launch_bounds__(SCAN_B) void scan_local_kernel(int n) {
    __shared__ int wsums[32];
    int t = threadIdx.x, lane = t & 31, w = t >> 5;
    int i = blockIdx.x * SCAN_B + t;
    int orig = (i < n) ? g_deg[i] : 0;
    int v = orig;
    #pragma unroll
    for (int o = 1; o < 32; o <<= 1) {
        int u = __shfl_up_sync(0xffffffffu, v, o);
        if (lane >= o) v += u;
    }
    if (lane == 31) wsums[w] = v;
    __syncthreads();
    if (w == 0) {
        int s = wsums[lane];
        #pragma unroll
        for (int o = 1; o < 32; o <<= 1) {
            int u = __shfl_up_sync(0xffffffffu, s, o);
            if (lane >= o) s += u;
        }
        wsums[lane] = s;
    }
    __syncthreads();
    int incl = v + ((w > 0) ? wsums[w - 1] : 0);
    if (i < n) g_rowptr[i] = incl - orig;             // exclusive
    if (t == SCAN_B - 1) g_bsums[blockIdx.x] = incl;  // block total
}

// stage 2 (fused): each block redundantly reduces block sums below it for its
// offset; also computes dinv and inits cursors.
__global__ __launch_bounds__(SCAN_B) void scan_add_fused_kernel(int n, int E, int nb) {
    __shared__ int sh[128];
    __shared__ int offset;
    int t = threadIdx.x;
    if (t < 128) sh[t] = (t < nb && t < (int)blockIdx.x) ? g_bsums[t] : 0;
    __syncthreads();
    if (t < 64) sh[t] += sh[t + 64];
    __syncthreads();
    if (t < 32) {
        int v = sh[t] + sh[t + 32];
        #pragma unroll
        for (int o = 16; o > 0; o >>= 1) v += __shfl_down_sync(0xffffffffu, v, o);
        if (t == 0) offset = v;
    }
    __syncthreads();
    int i = blockIdx.x * SCAN_B + t;
    if (i < n) {
        int r = g_rowptr[i] + offset;
        g_rowptr[i] = r;
        g_cursor[i] = r;
        s_dinv[i] = rsqrtf((float)g_deg[i] + 1.0f);   // +1 self loop
    }
    if (i == 0) g_rowptr[n] = E;
}

// counting-sort scatter of src ids into dst-contiguous segments (int4 reads)
__global__ void sort_kernel(const int* __restrict__ ei, int E) {
    int nE4 = E >> 2;
    int i = blockIdx.x * blockDim.x + threadIdx.x;
    if (i < nE4) {
        int4 s = __ldg(&((const int4*)ei)[i]);
        int4 d = __ldg(&((const int4*)(ei + E))[i]);
        g_srcsort[atomicAdd(&g_cursor[d.x], 1)] = s.x;
        g_srcsort[atomicAdd(&g_cursor[d.y], 1)] = s.y;
        g_srcsort[atomicAdd(&g_cursor[d.z], 1)] = s.z;
        g_srcsort[atomicAdd(&g_cursor[d.w], 1)] = s.w;
    }
    if (i == 0) {
        for (int e = E & ~3; e < E; e++)
            g_srcsort[atomicAdd(&g_cursor[ei[E + e]], 1)] = ei[e];
    }
}

// ---------------------------------------------------------------------------
// layer-2 GEMM (dinv epilogue applied)
__global__ __launch_bounds__(256) void gemm_scale_kernel(
    const float* __restrict__ X, const float* __restrict__ W, int n)
{
    __shared__ float4 ws[D * D4];
    __shared__ float4 xs[TILE_ROWS * D4];
    gemm_body(X, W, n, blockIdx.x * TILE_ROWS, /*apply_dinv=*/true, ws, xs);
}

// ---------------------------------------------------------------------------
// Gather-aggregate + epilogue. 16 threads/node, one float4 column each.
// SRC_SCALED: s_g already holds dinv-scaled rows (layer 2).
// !SRC_SCALED: s_g holds raw h; apply dinv[s] at gather (layer 1).
template <bool SRC_SCALED>
__global__ __launch_bounds__(256) void aggregate_kernel(
    const float* __restrict__ b, float* __restrict__ out, int n)
{
    int idx = blockIdx.x * blockDim.x + threadIdx.x;
    int v = idx >> 4;
    if (v >= n) return;
    int j = idx & 15;

    float dvv = __ldg(&s_dinv[v]);
    float4 acc = __ldg(&s_g[v * D4 + j]);              // self loop
    if (!SRC_SCALED) { acc.x *= dvv; acc.y *= dvv; acc.z *= dvv; acc.w *= dvv; }

    int beg = __ldg(&g_rowptr[v]);
    int end = __ldg(&g_rowptr[v + 1]);

    int k = beg;
    #pragma unroll 1
    for (; k + 4 <= end; k += 4) {
        int s0 = __ldg(&g_srcsort[k + 0]);
        int s1 = __ldg(&g_srcsort[k + 1]);
        int s2 = __ldg(&g_srcsort[k + 2]);
        int s3 = __ldg(&g_srcsort[k + 3]);
        float4 a0 = __ldg(&s_g[s0 * D4 + j]);
        float4 a1 = __ldg(&s_g[s1 * D4 + j]);
        float4 a2 = __ldg(&s_g[s2 * D4 + j]);
        float4 a3 = __ldg(&s_g[s3 * D4 + j]);
        if (!SRC_SCALED) {
            float d0 = __ldg(&s_dinv[s0]), d1 = __ldg(&s_dinv[s1]);
            float d2 = __ldg(&s_dinv[s2]), d3 = __ldg(&s_dinv[s3]);
            acc.x += a0.x * d0 + a1.x * d1 + a2.x * d2 + a3.x * d3;
            acc.y += a0.y * d0 + a1.y * d1 + a2.y * d2 + a3.y * d3;
            acc.z += a0.z * d0 + a1.z * d1 + a2.z * d2 + a3.z * d3;
            acc.w += a0.w * d0 + a1.w * d1 + a2.w * d2 + a3.w * d3;
        } else {
            acc.x += (a0.x + a1.x) + (a2.x + a3.x);
            acc.y += (a0.y + a1.y) + (a2.y + a3.y);
            acc.z += (a0.z + a1.z) + (a2.z + a3.z);
            acc.w += (a0.w + a1.w) + (a2.w + a3.w);
        }
    }
    for (; k < end; k++) {
        int s = __ldg(&g_srcsort[k]);
        float4 a = __ldg(&s_g[s * D4 + j]);
        float ds = SRC_SCALED ? 1.0f : __ldg(&s_dinv[s]);
        acc.x += a.x * ds; acc.y += a.y * ds; acc.z += a.z * ds; acc.w += a.w * ds;
    }

    float4 bb = __ldg(&((const float4*)b)[j]);
    float4 o;
    o.x = fmaxf(fmaf(acc.x, dvv, bb.x), 0.f);
    o.y = fmaxf(fmaf(acc.y, dvv, bb.y), 0.f);
    o.z = fmaxf(fmaf(acc.z, dvv, bb.z), 0.f);
    o.w = fmaxf(fmaf(acc.w, dvv, bb.w), 0.f);
    ((float4*)out)[v * D4 + j] = o;
}

// ---------------------------------------------------------------------------
extern "C" void kernel_launch(void* const* d_in, const int* in_sizes, int n_in,
                              void* d_out, int out_size)
{
    const float* x  = (const float*)d_in[0];
    const int*   ei = (const int*)d_in[1];      // int32 (JAX x64 disabled)
    const float* W1 = (const float*)d_in[2];
    const float* b1 = (const float*)d_in[3];
    const float* W2 = (const float*)d_in[4];
    const float* b2 = (const float*)d_in[5];
    float* out = (float*)d_out;

    const int n = in_sizes[0] / D;        // 100000
    const int E = in_sizes[1] / 2;        // 1000000

    const int nb_sc   = (n + SCAN_B - 1) / SCAN_B;
    const int nb_gmm  = (n + TILE_ROWS - 1) / TILE_ROWS;
    const int nb_e4   = ((E >> 2) + 255) / 256;
    const int nb_agg  = (n * D4 + 255) / 256;

    // zero degree counters via a graph memset node
    void* degp = nullptr;
    cudaGetSymbolAddress(&degp, g_deg);
    cudaMemsetAsync(degp, 0, (size_t)n * sizeof(int));

    float* y = nullptr;
    cudaGetSymbolAddress((void**)&y, s_y);

    // GEMM1 (unscaled) co-resident with dst histogram
    gemm1_hist_kernel<<<nb_gmm + nb_e4, 256>>>(x, W1, ei, n, E, nb_gmm);

    // scan + dinv + cursors, then counting sort
    scan_local_kernel<<<nb_sc, SCAN_B>>>(n);
    scan_add_fused_kernel<<<nb_sc, SCAN_B>>>(n, E, nb_sc);
    sort_kernel<<<nb_e4, 256>>>(ei, E);

    // layer 1 aggregation (applies dinv at gather)
    aggregate_kernel<false><<<nb_agg, 256>>>(b1, y, n);

    // layer 2
    gemm_scale_kernel<<<nb_gmm, 256>>>(y, W2, n);
    aggregate_kernel<true><<<nb_agg, 256>>>(b2, out, n);
}

// round 7
// speedup vs baseline: 1.0775x; 1.0775x over previous
#include <cuda_runtime.h>
#include <cuda_fp16.h>
#include <cstdint>

#define N_MAX 100000
#define E_MAX 1000000
#define D 64
#define D4 16               // D/4 float4 per row
#define TILE_ROWS 128
#define SCAN_B 1024

// Scratch (static device globals — no allocations allowed)
__device__ int    g_deg     [N_MAX];
__device__ int    g_rowptr  [N_MAX + 1];
__device__ int    g_cursor  [N_MAX];
__device__ int    g_srcsort [E_MAX];
__device__ int    g_bsums   [128];
__device__ float  s_dinv    [N_MAX];
__device__ uint4  s_h       [N_MAX * 8];    // fp16 features: 64 halves = 8 uint4/row
__device__ float4 s_y       [N_MAX * D4];   // layer-1 output (fp32)

// ---------------------------------------------------------------------------
// edge_index is INT32 on device (JAX x64 disabled canonicalizes int64->int32).
__global__ void hist_kernel(const int* __restrict__ ei, int E) {
    int e = blockIdx.x * blockDim.x + threadIdx.x;
    if (e < E) atomicAdd(&g_deg[ei[E + e]], 1);
}

// exclusive scan, stage 1: shuffle-based per-block scan + block totals
__global__ __launch_bounds__(SCAN_B) void scan_local_kernel(int n) {
    __shared__ int wsums[32];
    int t = threadIdx.x, lane = t & 31, w = t >> 5;
    int i = blockIdx.x * SCAN_B + t;
    int orig = (i < n) ? g_deg[i] : 0;
    int v = orig;
    #pragma unroll
    for (int o = 1; o < 32; o <<= 1) {
        int u = __shfl_up_sync(0xffffffffu, v, o);
        if (lane >= o) v += u;
    }
    if (lane == 31) wsums[w] = v;
    __syncthreads();
    if (w == 0) {
        int s = wsums[lane];
        #pragma unroll
        for (int o = 1; o < 32; o <<= 1) {
            int u = __shfl_up_sync(0xffffffffu, s, o);
            if (lane >= o) s += u;
        }
        wsums[lane] = s;
    }
    __syncthreads();
    int incl = v + ((w > 0) ? wsums[w - 1] : 0);
    if (i < n) g_rowptr[i] = incl - orig;             // exclusive
    if (t == SCAN_B - 1) g_bsums[blockIdx.x] = incl;  // block total
}

// stage 2 (fused): each block redundantly reduces block sums below it for its
// offset; also computes dinv and inits cursors.
__global__ __launch_bounds__(SCAN_B) void scan_add_fused_kernel(int n, int E, int nb) {
    __shared__ int sh[128];
    __shared__ int offset;
    int t = threadIdx.x;
    if (t < 128) sh[t] = (t < nb && t < (int)blockIdx.x) ? g_bsums[t] : 0;
    __syncthreads();
    if (t < 64) sh[t] += sh[t + 64];
    __syncthreads();
    if (t < 32) {
        int v = sh[t] + sh[t + 32];
        #pragma unroll
        for (int o = 16; o > 0; o >>= 1) v += __shfl_down_sync(0xffffffffu, v, o);
        if (t == 0) offset = v;
    }
    __syncthreads();
    int i = blockIdx.x * SCAN_B + t;
    if (i < n) {
        int r = g_rowptr[i] + offset;
        g_rowptr[i] = r;
        g_cursor[i] = r;
        s_dinv[i] = rsqrtf((float)g_deg[i] + 1.0f);   // +1 self loop
    }
    if (i == 0) g_rowptr[n] = E;
}

// counting-sort scatter of src ids into dst-contiguous segments (scalar: max TLP)
__global__ void sort_kernel(const int* __restrict__ ei, int E) {
    int e = blockIdx.x * blockDim.x + threadIdx.x;
    if (e < E) {
        int src = ei[e];
        int dst = ei[E + e];
        int pos = atomicAdd(&g_cursor[dst], 1);
        g_srcsort[pos] = src;
    }
}

// ---------------------------------------------------------------------------
// h = dinv[row] * (X @ W), stored as fp16 into s_h.
// 256 threads, 128 rows/block. Thread = 8 rows x 4 cols.
__global__ __launch_bounds__(256) void gemm_scale_kernel(
    const float* __restrict__ X, const float* __restrict__ W, int n)
{
    __shared__ float4 ws[D * D4];          // W: 64x64
    __shared__ float4 xs[TILE_ROWS * D4];  // X tile

    const int tid  = threadIdx.x;
    const int row0 = blockIdx.x * TILE_ROWS;

    const float4* W4 = (const float4*)W;
    #pragma unroll
    for (int i = tid; i < D * D4; i += 256) ws[i] = __ldg(&W4[i]);

    const float4* X4 = (const float4*)X;
    #pragma unroll
    for (int i = tid; i < TILE_ROWS * D4; i += 256) {
        int rr = i >> 4;
        float4 v = make_float4(0.f, 0.f, 0.f, 0.f);
        if (row0 + rr < n) v = __ldg(&X4[(row0 + rr) * D4 + (i & 15)]);
        xs[i] = v;
    }
    __syncthreads();

    const int cg = tid & 15;   // col group: cols cg*4..cg*4+3
    const int rg = tid >> 4;   // row group: rows rg*8..rg*8+7

    float acc[8][4];
    #pragma unroll
    for (int r = 0; r < 8; r++)
        #pragma unroll
        for (int c = 0; c < 4; c++) acc[r][c] = 0.f;

    #pragma unroll 2
    for (int k = 0; k < D; k += 4) {
        float4 w0 = ws[(k + 0) * D4 + cg];
        float4 w1 = ws[(k + 1) * D4 + cg];
        float4 w2 = ws[(k + 2) * D4 + cg];
        float4 w3 = ws[(k + 3) * D4 + cg];
        #pragma unroll
        for (int r = 0; r < 8; r++) {
            float4 xv = xs[(rg * 8 + r) * D4 + (k >> 2)];
            acc[r][0] += xv.x * w0.x + xv.y * w1.x + xv.z * w2.x + xv.w * w3.x;
            acc[r][1] += xv.x * w0.y + xv.y * w1.y + xv.z * w2.y + xv.w * w3.y;
            acc[r][2] += xv.x * w0.z + xv.y * w1.z + xv.z * w2.z + xv.w * w3.z;
            acc[r][3] += xv.x * w0.w + xv.y * w1.w + xv.z * w2.w + xv.w * w3.w;
        }
    }

    uint2* S2 = (uint2*)s_h;   // row = 16 uint2 (64 halves)
    #pragma unroll
    for (int r = 0; r < 8; r++) {
        int row = row0 + rg * 8 + r;
        if (row < n) {
            float dv = s_dinv[row];
            __half2 p0 = __floats2half2_rn(acc[r][0] * dv, acc[r][1] * dv);
            __half2 p1 = __floats2half2_rn(acc[r][2] * dv, acc[r][3] * dv);
            uint2 u;
            u.x = *(unsigned int*)&p0;
            u.y = *(unsigned int*)&p1;
            S2[row * 16 + cg] = u;
        }
    }
}

// ---------------------------------------------------------------------------
__device__ __forceinline__ void acc_add8(float acc[8], uint4 u) {
    float2 f0 = __half22float2(*(__half2*)&u.x);
    float2 f1 = __half22float2(*(__half2*)&u.y);
    float2 f2 = __half22float2(*(__half2*)&u.z);
    float2 f3 = __half22float2(*(__half2*)&u.w);
    acc[0] += f0.x; acc[1] += f0.y; acc[2] += f1.x; acc[3] += f1.y;
    acc[4] += f2.x; acc[5] += f2.y; acc[6] += f3.x; acc[7] += f3.y;
}

// Gather-aggregate + epilogue: out[v] = relu(dinv[v]*(h[v] + sum h[src]) + b)
// 8 threads per node, one uint4 (8 halves) each. fp32 accumulation.
__global__ __launch_bounds__(256) void aggregate_kernel(
    const float* __restrict__ b, float* __restrict__ out, int n)
{
    int idx = blockIdx.x * blockDim.x + threadIdx.x;
    int v = idx >> 3;
    if (v >= n) return;
    int j = idx & 7;

    float acc[8];
    #pragma unroll
    for (int c = 0; c < 8; c++) acc[c] = 0.f;
    acc_add8(acc, __ldg(&s_h[v * 8 + j]));             // self loop

    int beg = __ldg(&g_rowptr[v]);
    int end = __ldg(&g_rowptr[v + 1]);

    int k = beg;
    #pragma unroll 1
    for (; k + 4 <= end; k += 4) {
        int s0 = __ldg(&g_srcsort[k + 0]);
        int s1 = __ldg(&g_srcsort[k + 1]);
        int s2 = __ldg(&g_srcsort[k + 2]);
        int s3 = __ldg(&g_srcsort[k + 3]);
        uint4 u0 = __ldg(&s_h[s0 * 8 + j]);
        uint4 u1 = __ldg(&s_h[s1 * 8 + j]);
        uint4 u2 = __ldg(&s_h[s2 * 8 + j]);
        uint4 u3 = __ldg(&s_h[s3 * 8 + j]);
        acc_add8(acc, u0);
        acc_add8(acc, u1);
        acc_add8(acc, u2);
        acc_add8(acc, u3);
    }
    for (; k < end; k++) {
        int s = __ldg(&g_srcsort[k]);
        acc_add8(acc, __ldg(&s_h[s * 8 + j]));
    }

    float dv = __ldg(&s_dinv[v]);
    const float4* b4 = (const float4*)b;
    float4 bb0 = __ldg(&b4[j * 2 + 0]);
    float4 bb1 = __ldg(&b4[j * 2 + 1]);
    float4 o0, o1;
    o0.x = fmaxf(fmaf(acc[0], dv, bb0.x), 0.f);
    o0.y = fmaxf(fmaf(acc[1], dv, bb0.y), 0.f);
    o0.z = fmaxf(fmaf(acc[2], dv, bb0.z), 0.f);
    o0.w = fmaxf(fmaf(acc[3], dv, bb0.w), 0.f);
    o1.x = fmaxf(fmaf(acc[4], dv, bb1.x), 0.f);
    o1.y = fmaxf(fmaf(acc[5], dv, bb1.y), 0.f);
    o1.z = fmaxf(fmaf(acc[6], dv, bb1.z), 0.f);
    o1.w = fmaxf(fmaf(acc[7], dv, bb1.w), 0.f);
    float4* O4 = (float4*)out;
    O4[v * 16 + j * 2 + 0] = o0;
    O4[v * 16 + j * 2 + 1] = o1;
}

// ---------------------------------------------------------------------------
extern "C" void kernel_launch(void* const* d_in, const int* in_sizes, int n_in,
                              void* d_out, int out_size)
{
    const float* x  = (const float*)d_in[0];
    const int*   ei = (const int*)d_in[1];      // int32 (JAX x64 disabled)
    const float* W1 = (const float*)d_in[2];
    const float* b1 = (const float*)d_in[3];
    const float* W2 = (const float*)d_in[4];
    const float* b2 = (const float*)d_in[5];
    float* out = (float*)d_out;

    const int n = in_sizes[0] / D;        // 100000
    const int E = in_sizes[1] / 2;        // 1000000

    const int nb_e   = (E + 255) / 256;
    const int nb_sc  = (n + SCAN_B - 1) / SCAN_B;
    const int nb_gmm = (n + TILE_ROWS - 1) / TILE_ROWS;
    const int nb_agg = (n * 8 + 255) / 256;

    // zero degree counters via a graph memset node
    void* degp = nullptr;
    cudaGetSymbolAddress(&degp, g_deg);
    cudaMemsetAsync(degp, 0, (size_t)n * sizeof(int));

    float* y = nullptr;
    cudaGetSymbolAddress((void**)&y, s_y);

    // --- graph preprocessing (shared by both layers) ---
    hist_kernel<<<nb_e, 256>>>(ei, E);
    scan_local_kernel<<<nb_sc, SCAN_B>>>(n);
    scan_add_fused_kernel<<<nb_sc, SCAN_B>>>(n, E, nb_sc);
    sort_kernel<<<nb_e, 256>>>(ei, E);

    // layer 1
    gemm_scale_kernel<<<nb_gmm, 256>>>(x, W1, n);
    aggregate_kernel<<<nb_agg, 256>>>(b1, y, n);

    // layer 2
    gemm_scale_kernel<<<nb_gmm, 256>>>(y, W2, n);
    aggregate_kernel<<<nb_agg, 256>>>(b2, out, n);
}

// round 8
// speedup vs baseline: 1.1132x; 1.0331x over previous
#include <cuda_runtime.h>
#include <cuda_fp16.h>
#include <cstdint>

#define N_MAX 100000
#define E_MAX 1000000
#define D 64
#define D4 16               // D/4 float4 per row
#define TILE_ROWS 128       // gemm2 tile
#define TR2 64              // hetero gemm tile (smaller smem for co-residency)
#define SCAN_B 1024

// Scratch (static device globals — no allocations allowed)
__device__ int    g_deg     [N_MAX];
__device__ int    g_rowptr  [N_MAX + 1];
__device__ int    g_cursor  [N_MAX];
__device__ int    g_srcsort [E_MAX];
__device__ int    g_bsums   [128];
__device__ float  s_dinv    [N_MAX];
__device__ uint4  s_h       [N_MAX * 8];    // fp16 features: 64 halves = 8 uint4/row
__device__ float4 s_y       [N_MAX * D4];   // layer-1 output (fp32)

// ---------------------------------------------------------------------------
// edge_index is INT32 on device (JAX x64 disabled canonicalizes int64->int32).
__global__ void hist_kernel(const int* __restrict__ ei, int E) {
    int e = blockIdx.x * blockDim.x + threadIdx.x;
    if (e < E) atomicAdd(&g_deg[ei[E + e]], 1);
}

// exclusive scan, stage 1: shuffle-based per-block scan + block totals
__global__ __launch_bounds__(SCAN_B) void scan_local_kernel(int n) {
    __shared__ int wsums[32];
    int t = threadIdx.x, lane = t & 31, w = t >> 5;
    int i = blockIdx.x * SCAN_B + t;
    int orig = (i < n) ? g_deg[i] : 0;
    int v = orig;
    #pragma unroll
    for (int o = 1; o < 32; o <<= 1) {
        int u = __shfl_up_sync(0xffffffffu, v, o);
        if (lane >= o) v += u;
    }
    if (lane == 31) wsums[w] = v;
    __syncthreads();
    if (w == 0) {
        int s = wsums[lane];
        #pragma unroll
        for (int o = 1; o < 32; o <<= 1) {
            int u = __shfl_up_sync(0xffffffffu, s, o);
            if (lane >= o) s += u;
        }
        wsums[lane] = s;
    }
    __syncthreads();
    int incl = v + ((w > 0) ? wsums[w - 1] : 0);
    if (i < n) g_rowptr[i] = incl - orig;             // exclusive
    if (t == SCAN_B - 1) g_bsums[blockIdx.x] = incl;  // block total
}

// stage 2 (fused): each block redundantly reduces block sums below it for its
// offset; also computes dinv and inits cursors.
__global__ __launch_bounds__(SCAN_B) void scan_add_fused_kernel(int n, int E, int nb) {
    __shared__ int sh[128];
    __shared__ int offset;
    int t = threadIdx.x;
    if (t < 128) sh[t] = (t < nb && t < (int)blockIdx.x) ? g_bsums[t] : 0;
    __syncthreads();
    if (t < 64) sh[t] += sh[t + 64];
    __syncthreads();
    if (t < 32) {
        int v = sh[t] + sh[t + 32];
        #pragma unroll
        for (int o = 16; o > 0; o >>= 1) v += __shfl_down_sync(0xffffffffu, v, o);
        if (t == 0) offset = v;
    }
    __syncthreads();
    int i = blockIdx.x * SCAN_B + t;
    if (i < n) {
        int r = g_rowptr[i] + offset;
        g_rowptr[i] = r;
        g_cursor[i] = r;
        s_dinv[i] = rsqrtf((float)g_deg[i] + 1.0f);   // +1 self loop
    }
    if (i == 0) g_rowptr[n] = E;
}

// ---------------------------------------------------------------------------
// fp16 store helper
__device__ __forceinline__ void store_row_fp16(
    int row, int cg, float a0, float a1, float a2, float a3)
{
    float dv = s_dinv[row];
    __half2 p0 = __floats2half2_rn(a0 * dv, a1 * dv);
    __half2 p1 = __floats2half2_rn(a2 * dv, a3 * dv);
    uint2 u;
    u.x = *(unsigned int*)&p0;
    u.y = *(unsigned int*)&p1;
    ((uint2*)s_h)[row * 16 + cg] = u;
}

// ---------------------------------------------------------------------------
// Heterogeneous launch: blocks [0, nb_sort) do the counting sort (latency-
// bound, long pole — scheduled first); blocks [nb_sort, +nb_gmm) do GEMM1
// with a 64-row tile (32KB smem -> 7 blocks/SM co-residency).
__global__ __launch_bounds__(256) void sort_gemm1_kernel(
    const float* __restrict__ X, const float* __restrict__ W,
    const int* __restrict__ ei, int n, int E, int nb_sort)
{
    __shared__ float4 ws[D * D4];     // 16KB
    __shared__ float4 xs[TR2 * D4];   // 16KB

    if ((int)blockIdx.x < nb_sort) {
        // ---- counting-sort scatter ----
        int e = blockIdx.x * 256 + threadIdx.x;
        if (e < E) {
            int src = ei[e];
            int dst = ei[E + e];
            int pos = atomicAdd(&g_cursor[dst], 1);
            g_srcsort[pos] = src;
        }
        return;
    }

    // ---- GEMM1: h = dinv * (X @ W1), fp16 store ----
    const int tid  = threadIdx.x;
    const int row0 = ((int)blockIdx.x - nb_sort) * TR2;

    const float4* W4 = (const float4*)W;
    #pragma unroll
    for (int i = tid; i < D * D4; i += 256) ws[i] = __ldg(&W4[i]);

    const float4* X4 = (const float4*)X;
    #pragma unroll
    for (int i = tid; i < TR2 * D4; i += 256) {
        int rr = i >> 4;
        float4 v = make_float4(0.f, 0.f, 0.f, 0.f);
        if (row0 + rr < n) v = __ldg(&X4[(row0 + rr) * D4 + (i & 15)]);
        xs[i] = v;
    }
    __syncthreads();

    const int cg = tid & 15;   // col group
    const int rg = tid >> 4;   // row group: 4 rows each

    float acc[4][4];
    #pragma unroll
    for (int r = 0; r < 4; r++)
        #pragma unroll
        for (int c = 0; c < 4; c++) acc[r][c] = 0.f;

    #pragma unroll 2
    for (int k = 0; k < D; k += 4) {
        float4 w0 = ws[(k + 0) * D4 + cg];
        float4 w1 = ws[(k + 1) * D4 + cg];
        float4 w2 = ws[(k + 2) * D4 + cg];
        float4 w3 = ws[(k + 3) * D4 + cg];
        #pragma unroll
        for (int r = 0; r < 4; r++) {
            float4 xv = xs[(rg * 4 + r) * D4 + (k >> 2)];
            acc[r][0] += xv.x * w0.x + xv.y * w1.x + xv.z * w2.x + xv.w * w3.x;
            acc[r][1] += xv.x * w0.y + xv.y * w1.y + xv.z * w2.y + xv.w * w3.y;
            acc[r][2] += xv.x * w0.z + xv.y * w1.z + xv.z * w2.z + xv.w * w3.z;
            acc[r][3] += xv.x * w0.w + xv.y * w1.w + xv.z * w2.w + xv.w * w3.w;
        }
    }

    #pragma unroll
    for (int r = 0; r < 4; r++) {
        int row = row0 + rg * 4 + r;
        if (row < n)
            store_row_fp16(row, cg, acc[r][0], acc[r][1], acc[r][2], acc[r][3]);
    }
}

// ---------------------------------------------------------------------------
// layer-2 GEMM: h = dinv * (Y @ W2), fp16 store. 128-row tile (runs alone).
__global__ __launch_bounds__(256) void gemm_scale_kernel(
    const float* __restrict__ X, const float* __restrict__ W, int n)
{
    __shared__ float4 ws[D * D4];          // 16KB
    __shared__ float4 xs[TILE_ROWS * D4];  // 32KB

    const int tid  = threadIdx.x;
    const int row0 = blockIdx.x * TILE_ROWS;

    const float4* W4 = (const float4*)W;
    #pragma unroll
    for (int i = tid; i < D * D4; i += 256) ws[i] = __ldg(&W4[i]);

    const float4* X4 = (const float4*)X;
    #pragma unroll
    for (int i = tid; i < TILE_ROWS * D4; i += 256) {
        int rr = i >> 4;
        float4 v = make_float4(0.f, 0.f, 0.f, 0.f);
        if (row0 + rr < n) v = __ldg(&X4[(row0 + rr) * D4 + (i & 15)]);
        xs[i] = v;
    }
    __syncthreads();

    const int cg = tid & 15;
    const int rg = tid >> 4;

    float acc[8][4];
    #pragma unroll
    for (int r = 0; r < 8; r++)
        #pragma unroll
        for (int c = 0; c < 4; c++) acc[r][c] = 0.f;

    #pragma unroll 2
    for (int k = 0; k < D; k += 4) {
        float4 w0 = ws[(k + 0) * D4 + cg];
        float4 w1 = ws[(k + 1) * D4 + cg];
        float4 w2 = ws[(k + 2) * D4 + cg];
        float4 w3 = ws[(k + 3) * D4 + cg];
        #pragma unroll
        for (int r = 0; r < 8; r++) {
            float4 xv = xs[(rg * 8 + r) * D4 + (k >> 2)];
            acc[r][0] += xv.x * w0.x + xv.y * w1.x + xv.z * w2.x + xv.w * w3.x;
            acc[r][1] += xv.x * w0.y + xv.y * w1.y + xv.z * w2.y + xv.w * w3.y;
            acc[r][2] += xv.x * w0.z + xv.y * w1.z + xv.z * w2.z + xv.w * w3.z;
            acc[r][3] += xv.x * w0.w + xv.y * w1.w + xv.z * w2.w + xv.w * w3.w;
        }
    }

    #pragma unroll
    for (int r = 0; r < 8; r++) {
        int row = row0 + rg * 8 + r;
        if (row < n)
            store_row_fp16(row, cg, acc[r][0], acc[r][1], acc[r][2], acc[r][3]);
    }
}

// ---------------------------------------------------------------------------
__device__ __forceinline__ void acc_add8(float acc[8], uint4 u) {
    float2 f0 = __half22float2(*(__half2*)&u.x);
    float2 f1 = __half22float2(*(__half2*)&u.y);
    float2 f2 = __half22float2(*(__half2*)&u.z);
    float2 f3 = __half22float2(*(__half2*)&u.w);
    acc[0] += f0.x; acc[1] += f0.y; acc[2] += f1.x; acc[3] += f1.y;
    acc[4] += f2.x; acc[5] += f2.y; acc[6] += f3.x; acc[7] += f3.y;
}

// Gather-aggregate + epilogue: out[v] = relu(dinv[v]*(h[v] + sum h[src]) + b)
// 8 threads per node, one uint4 (8 halves) each. fp32 accumulation.
__global__ __launch_bounds__(256) void aggregate_kernel(
    const float* __restrict__ b, float* __restrict__ out, int n)
{
    int idx = blockIdx.x * blockDim.x + threadIdx.x;
    int v = idx >> 3;
    if (v >= n) return;
    int j = idx & 7;

    float acc[8];
    #pragma unroll
    for (int c = 0; c < 8; c++) acc[c] = 0.f;
    acc_add8(acc, __ldg(&s_h[v * 8 + j]));             // self loop

    int beg = __ldg(&g_rowptr[v]);
    int end = __ldg(&g_rowptr[v + 1]);

    int k = beg;
    #pragma unroll 1
    for (; k + 4 <= end; k += 4) {
        int s0 = __ldg(&g_srcsort[k + 0]);
        int s1 = __ldg(&g_srcsort[k + 1]);
        int s2 = __ldg(&g_srcsort[k + 2]);
        int s3 = __ldg(&g_srcsort[k + 3]);
        uint4 u0 = __ldg(&s_h[s0 * 8 + j]);
        uint4 u1 = __ldg(&s_h[s1 * 8 + j]);
        uint4 u2 = __ldg(&s_h[s2 * 8 + j]);
        uint4 u3 = __ldg(&s_h[s3 * 8 + j]);
        acc_add8(acc, u0);
        acc_add8(acc, u1);
        acc_add8(acc, u2);
        acc_add8(acc, u3);
    }
    for (; k < end; k++) {
        int s = __ldg(&g_srcsort[k]);
        acc_add8(acc, __ldg(&s_h[s * 8 + j]));
    }

    float dv = __ldg(&s_dinv[v]);
    const float4* b4 = (const float4*)b;
    float4 bb0 = __ldg(&b4[j * 2 + 0]);
    float4 bb1 = __ldg(&b4[j * 2 + 1]);
    float4 o0, o1;
    o0.x = fmaxf(fmaf(acc[0], dv, bb0.x), 0.f);
    o0.y = fmaxf(fmaf(acc[1], dv, bb0.y), 0.f);
    o0.z = fmaxf(fmaf(acc[2], dv, bb0.z), 0.f);
    o0.w = fmaxf(fmaf(acc[3], dv, bb0.w), 0.f);
    o1.x = fmaxf(fmaf(acc[4], dv, bb1.x), 0.f);
    o1.y = fmaxf(fmaf(acc[5], dv, bb1.y), 0.f);
    o1.z = fmaxf(fmaf(acc[6], dv, bb1.z), 0.f);
    o1.w = fmaxf(fmaf(acc[7], dv, bb1.w), 0.f);
    float4* O4 = (float4*)out;
    O4[v * 16 + j * 2 + 0] = o0;
    O4[v * 16 + j * 2 + 1] = o1;
}

// ---------------------------------------------------------------------------
extern "C" void kernel_launch(void* const* d_in, const int* in_sizes, int n_in,
                              void* d_out, int out_size)
{
    const float* x  = (const float*)d_in[0];
    const int*   ei = (const int*)d_in[1];      // int32 (JAX x64 disabled)
    const float* W1 = (const float*)d_in[2];
    const float* b1 = (const float*)d_in[3];
    const float* W2 = (const float*)d_in[4];
    const float* b2 = (const float*)d_in[5];
    float* out = (float*)d_out;

    const int n = in_sizes[0] / D;        // 100000
    const int E = in_sizes[1] / 2;        // 1000000

    const int nb_e    = (E + 255) / 256;
    const int nb_sc   = (n + SCAN_B - 1) / SCAN_B;
    const int nb_gmm  = (n + TILE_ROWS - 1) / TILE_ROWS;
    const int nb_gmm2 = (n + TR2 - 1) / TR2;
    const int nb_agg  = (n * 8 + 255) / 256;

    // zero degree counters via a graph memset node
    void* degp = nullptr;
    cudaGetSymbolAddress(&degp, g_deg);
    cudaMemsetAsync(degp, 0, (size_t)n * sizeof(int));

    float* y = nullptr;
    cudaGetSymbolAddress((void**)&y, s_y);

    // --- graph preprocessing ---
    hist_kernel<<<nb_e, 256>>>(ei, E);
    scan_local_kernel<<<nb_sc, SCAN_B>>>(n);
    scan_add_fused_kernel<<<nb_sc, SCAN_B>>>(n, E, nb_sc);

    // sort (long pole) co-resident with GEMM1 — independent after scan_add
    sort_gemm1_kernel<<<nb_e + nb_gmm2, 256>>>(x, W1, ei, n, E, nb_e);

    // layer 1 aggregation
    aggregate_kernel<<<nb_agg, 256>>>(b1, y, n);

    // layer 2
    gemm_scale_kernel<<<nb_gmm, 256>>>(y, W2, n);
    aggregate_kernel<<<nb_agg, 256>>>(b2, out, n);
}